// round 2
// baseline (speedup 1.0000x reference)
#include <cuda_runtime.h>
#include <cuda_bf16.h>
#include <math.h>

// Problem dims
#define BB 64
#define NN 512
#define DD 256
#define HH 512
#define MAX_ITER 20

// M = B*N rows for the Z gemm
#define ZM (BB * NN)          // 32768

// Scratch (allocation-free: __device__ globals)
__device__ float g_Z[(size_t)ZM * HH];   // 64 MiB: Z[b,n,h] = V@W1v + b1
__device__ float g_q[BB * NN];
__device__ float g_u[BB * HH];

// ---------------------------------------------------------------------------
// Kernel 1: Z = V @ W1v + b1   (M=32768, K=256, N=512), TF32 mma.sync
// CTA tile 128x128, BK=32, 8 warps (4x2), warp tile 32x64, m16n8k8
// ---------------------------------------------------------------------------
__device__ __forceinline__ unsigned f2tf32(float x) {
    unsigned r;
    asm("cvt.rna.tf32.f32 %0, %1;" : "=r"(r) : "f"(x));
    return r;
}

__global__ __launch_bounds__(256) void zgemm_kernel(
    const float* __restrict__ V,    // [ZM, 256]
    const float* __restrict__ W1,   // [512, 512]; top 256 rows = W1v
    const float* __restrict__ b1)   // [512]
{
    __shared__ unsigned As[128][33];   // [m][k]
    __shared__ unsigned Bs[32][136];   // [k][n]

    const int tid   = threadIdx.x;
    const int warp  = tid >> 5;
    const int lane  = tid & 31;
    const int g     = lane >> 2;   // groupID 0..7
    const int tg    = lane & 3;    // thread-in-group 0..3
    const int warpM = warp >> 1;   // 0..3
    const int warpN = warp & 1;    // 0..1

    const int blockN = blockIdx.x;   // 0..3
    const int blockM = blockIdx.y;   // 0..255

    float c[2][8][4];
    #pragma unroll
    for (int mt = 0; mt < 2; mt++)
        #pragma unroll
        for (int nt = 0; nt < 8; nt++)
            #pragma unroll
            for (int i = 0; i < 4; i++) c[mt][nt][i] = 0.f;

    for (int k0 = 0; k0 < DD; k0 += 32) {
        // load A tile 128x32 (fp32 -> tf32 bits)
        #pragma unroll
        for (int t = 0; t < 16; t++) {
            int idx = tid + t * 256;
            int r = idx >> 5, cidx = idx & 31;
            float v = V[(size_t)(blockM * 128 + r) * DD + k0 + cidx];
            As[r][cidx] = f2tf32(v);
        }
        // load B tile 32x128
        #pragma unroll
        for (int t = 0; t < 16; t++) {
            int idx = tid + t * 256;
            int r = idx >> 7, cidx = idx & 127;
            float v = W1[(size_t)(k0 + r) * HH + blockN * 128 + cidx];
            Bs[r][cidx] = f2tf32(v);
        }
        __syncthreads();

        #pragma unroll
        for (int kk = 0; kk < 32; kk += 8) {
            unsigned a[2][4];
            #pragma unroll
            for (int mt = 0; mt < 2; mt++) {
                int ar = warpM * 32 + mt * 16 + g;
                a[mt][0] = As[ar][kk + tg];
                a[mt][1] = As[ar + 8][kk + tg];
                a[mt][2] = As[ar][kk + tg + 4];
                a[mt][3] = As[ar + 8][kk + tg + 4];
            }
            #pragma unroll
            for (int nt = 0; nt < 8; nt++) {
                int bc = warpN * 64 + nt * 8 + g;
                unsigned b0 = Bs[kk + tg][bc];
                unsigned bq = Bs[kk + tg + 4][bc];
                #pragma unroll
                for (int mt = 0; mt < 2; mt++) {
                    asm volatile(
                        "mma.sync.aligned.m16n8k8.row.col.f32.tf32.tf32.f32 "
                        "{%0,%1,%2,%3}, {%4,%5,%6,%7}, {%8,%9}, {%0,%1,%2,%3};"
                        : "+f"(c[mt][nt][0]), "+f"(c[mt][nt][1]),
                          "+f"(c[mt][nt][2]), "+f"(c[mt][nt][3])
                        : "r"(a[mt][0]), "r"(a[mt][1]), "r"(a[mt][2]), "r"(a[mt][3]),
                          "r"(b0), "r"(bq));
                }
            }
        }
        __syncthreads();
    }

    // epilogue: Z = c + b1[col]
    #pragma unroll
    for (int mt = 0; mt < 2; mt++) {
        int row0 = blockM * 128 + warpM * 32 + mt * 16 + g;
        #pragma unroll
        for (int nt = 0; nt < 8; nt++) {
            int col = blockN * 128 + warpN * 64 + nt * 8 + 2 * tg;
            float bA = b1[col], bBv = b1[col + 1];
            size_t base0 = (size_t)row0 * HH + col;
            size_t base1 = (size_t)(row0 + 8) * HH + col;
            g_Z[base0]     = c[mt][nt][0] + bA;
            g_Z[base0 + 1] = c[mt][nt][1] + bBv;
            g_Z[base1]     = c[mt][nt][2] + bA;
            g_Z[base1 + 1] = c[mt][nt][3] + bBv;
        }
    }
}

// ---------------------------------------------------------------------------
// Kernel 2 (per iter): pooled[b,:] = sum_n q[b,n]*V[b,n,:]  then
//                      u[b,h] = sum_d pooled[b,d]*W1p[d,h]
// one CTA per batch b, 256 threads
// ---------------------------------------------------------------------------
__global__ __launch_bounds__(256) void poolu_kernel(
    const float* __restrict__ q,    // [B, N]
    const float* __restrict__ V,    // [B, N, D]
    const float* __restrict__ W1,   // [512, 512]; rows 256..511 = W1p
    float* __restrict__ u)          // [B, H]
{
    const int b   = blockIdx.x;
    const int tid = threadIdx.x;

    __shared__ float qs[NN];
    __shared__ float4 part[4][64];
    __shared__ __align__(16) float pooled_s[DD];

    qs[tid]       = q[b * NN + tid];
    qs[tid + 256] = q[b * NN + tid + 256];
    __syncthreads();

    // phase 1: pooled
    const int d4 = tid & 63;       // float4 index into D
    const int ns = tid >> 6;       // 0..3, n-stripe
    const float4* __restrict__ V4 = (const float4*)V;
    float4 acc = make_float4(0.f, 0.f, 0.f, 0.f);
    #pragma unroll 4
    for (int n = ns; n < NN; n += 4) {
        float qv = qs[n];
        float4 v = V4[(size_t)(b * NN + n) * (DD / 4) + d4];
        acc.x += qv * v.x; acc.y += qv * v.y;
        acc.z += qv * v.z; acc.w += qv * v.w;
    }
    part[ns][d4] = acc;
    __syncthreads();
    if (tid < 64) {
        float4 s0 = part[0][tid], s1 = part[1][tid],
               s2 = part[2][tid], s3 = part[3][tid];
        float4 s = make_float4(s0.x + s1.x + s2.x + s3.x,
                               s0.y + s1.y + s2.y + s3.y,
                               s0.z + s1.z + s2.z + s3.z,
                               s0.w + s1.w + s2.w + s3.w);
        ((float4*)pooled_s)[tid] = s;
    }
    __syncthreads();

    // phase 2: u[b,h] for h = tid and tid+256
    const float* __restrict__ W1p = W1 + (size_t)DD * HH;  // rows 256..
    float a0 = 0.f, a1 = 0.f;
    #pragma unroll 4
    for (int d = 0; d < DD; d++) {
        float p = pooled_s[d];
        a0 += p * W1p[(size_t)d * HH + tid];
        a1 += p * W1p[(size_t)d * HH + tid + 256];
    }
    u[b * HH + tid]       = a0;
    u[b * HH + tid + 256] = a1;
}

// ---------------------------------------------------------------------------
// Kernel 3 (per iter): q'[b,n] = sigmoid( sum_h relu(Z[b,n,h]+u[b,h])*w2[h] + b2 )
// CTA: 256 thr, 8 warps; each warp handles 4 rows (n). 1024 CTAs.
// ---------------------------------------------------------------------------
__global__ __launch_bounds__(256) void score_kernel(
    const float* __restrict__ u,    // [B, H]
    const float* __restrict__ W2,   // [H]
    const float* __restrict__ b2,   // [1]
    float* __restrict__ qout)       // [B, N]
{
    const int blk = blockIdx.x;            // 0..1023
    const int b   = blk >> 4;
    const int nb  = (blk & 15) * 32;
    const int tid = threadIdx.x;
    const int w   = tid >> 5;
    const int l   = tid & 31;

    __shared__ float4 us4[HH / 4];
    __shared__ float4 w24[HH / 4];
    if (tid < HH / 4) {
        us4[tid] = ((const float4*)(u + b * HH))[tid];
        w24[tid] = ((const float4*)W2)[tid];
    }
    __syncthreads();

    const float b2v = b2[0];

    #pragma unroll
    for (int r = 0; r < 4; r++) {
        const int n = nb + w * 4 + r;
        const float4* __restrict__ z4 =
            (const float4*)(g_Z + (size_t)(b * NN + n) * HH);
        float acc = 0.f;
        #pragma unroll
        for (int k = 0; k < 4; k++) {
            int idx = l + 32 * k;
            float4 z  = z4[idx];
            float4 uu = us4[idx];
            float4 ww = w24[idx];
            acc += fmaxf(z.x + uu.x, 0.f) * ww.x;
            acc += fmaxf(z.y + uu.y, 0.f) * ww.y;
            acc += fmaxf(z.z + uu.z, 0.f) * ww.z;
            acc += fmaxf(z.w + uu.w, 0.f) * ww.w;
        }
        #pragma unroll
        for (int off = 16; off; off >>= 1)
            acc += __shfl_xor_sync(0xffffffffu, acc, off);
        if (l == 0) {
            float s = acc + b2v;
            qout[b * NN + n] = 1.f / (1.f + expf(-s));
        }
    }
}

// ---------------------------------------------------------------------------
extern "C" void kernel_launch(void* const* d_in, const int* in_sizes, int n_in,
                              void* d_out, int out_size) {
    const float* q_init = (const float*)d_in[0];  // [B,N]   32768
    const float* V      = (const float*)d_in[1];  // [B,N,D] 8388608
    const float* W1     = (const float*)d_in[2];  // [2D,H]  262144
    const float* b1     = (const float*)d_in[3];  // [H]     512
    const float* W2     = (const float*)d_in[4];  // [H]     512
    const float* b2     = (const float*)d_in[5];  // [1]     1
    float* out = (float*)d_out;

    float* g_q_p;
    float* g_u_p;
    cudaGetSymbolAddress((void**)&g_q_p, g_q);
    cudaGetSymbolAddress((void**)&g_u_p, g_u);

    // One-time (per call): Z = V @ W1v + b1
    zgemm_kernel<<<dim3(4, 256), 256>>>(V, W1, b1);

    for (int it = 0; it < MAX_ITER; it++) {
        const float* qin = (it == 0) ? q_init : g_q_p;
        poolu_kernel<<<BB, 256>>>(qin, V, W1, g_u_p);
        float* qdst = (it == MAX_ITER - 1) ? out : g_q_p;
        score_kernel<<<BB * 16, 256>>>(g_u_p, W2, b2, qdst);
    }
}

// round 3
// speedup vs baseline: 1.5853x; 1.5853x over previous
#include <cuda_runtime.h>
#include <cuda_bf16.h>
#include <math.h>

// Problem dims
#define BB 64
#define NN 512
#define DD 256
#define HH 512
#define MAX_ITER 20
#define NSPLIT 8               // pooling splits over N

#define ZM (BB * NN)           // 32768

// Scratch (allocation-free: __device__ globals)
__device__ float g_Z[(size_t)ZM * HH];        // 64 MiB: Z[b,n,h] = V@W1v + b1
__device__ float g_q[BB * NN];
__device__ float g_u[BB * HH];
__device__ float g_part[BB * NSPLIT * DD];    // 512 KiB pooling partials

// ---------------------------------------------------------------------------
// Kernel 1 (once): Z = V @ W1v + b1   (M=32768, K=256, N=512), TF32 mma.sync
// ---------------------------------------------------------------------------
__device__ __forceinline__ unsigned f2tf32(float x) {
    unsigned r;
    asm("cvt.rna.tf32.f32 %0, %1;" : "=r"(r) : "f"(x));
    return r;
}

__global__ __launch_bounds__(256) void zgemm_kernel(
    const float* __restrict__ V,    // [ZM, 256]
    const float* __restrict__ W1,   // [512, 512]; top 256 rows = W1v
    const float* __restrict__ b1)   // [512]
{
    __shared__ unsigned As[128][33];   // [m][k]
    __shared__ unsigned Bs[32][136];   // [k][n]

    const int tid   = threadIdx.x;
    const int warp  = tid >> 5;
    const int lane  = tid & 31;
    const int g     = lane >> 2;
    const int tg    = lane & 3;
    const int warpM = warp >> 1;
    const int warpN = warp & 1;

    const int blockN = blockIdx.x;   // 0..3
    const int blockM = blockIdx.y;   // 0..255

    float c[2][8][4];
    #pragma unroll
    for (int mt = 0; mt < 2; mt++)
        #pragma unroll
        for (int nt = 0; nt < 8; nt++)
            #pragma unroll
            for (int i = 0; i < 4; i++) c[mt][nt][i] = 0.f;

    for (int k0 = 0; k0 < DD; k0 += 32) {
        #pragma unroll
        for (int t = 0; t < 16; t++) {
            int idx = tid + t * 256;
            int r = idx >> 5, cidx = idx & 31;
            As[r][cidx] = f2tf32(V[(size_t)(blockM * 128 + r) * DD + k0 + cidx]);
        }
        #pragma unroll
        for (int t = 0; t < 16; t++) {
            int idx = tid + t * 256;
            int r = idx >> 7, cidx = idx & 127;
            Bs[r][cidx] = f2tf32(W1[(size_t)(k0 + r) * HH + blockN * 128 + cidx]);
        }
        __syncthreads();

        #pragma unroll
        for (int kk = 0; kk < 32; kk += 8) {
            unsigned a[2][4];
            #pragma unroll
            for (int mt = 0; mt < 2; mt++) {
                int ar = warpM * 32 + mt * 16 + g;
                a[mt][0] = As[ar][kk + tg];
                a[mt][1] = As[ar + 8][kk + tg];
                a[mt][2] = As[ar][kk + tg + 4];
                a[mt][3] = As[ar + 8][kk + tg + 4];
            }
            #pragma unroll
            for (int nt = 0; nt < 8; nt++) {
                int bc = warpN * 64 + nt * 8 + g;
                unsigned b0 = Bs[kk + tg][bc];
                unsigned bq = Bs[kk + tg + 4][bc];
                #pragma unroll
                for (int mt = 0; mt < 2; mt++) {
                    asm volatile(
                        "mma.sync.aligned.m16n8k8.row.col.f32.tf32.tf32.f32 "
                        "{%0,%1,%2,%3}, {%4,%5,%6,%7}, {%8,%9}, {%0,%1,%2,%3};"
                        : "+f"(c[mt][nt][0]), "+f"(c[mt][nt][1]),
                          "+f"(c[mt][nt][2]), "+f"(c[mt][nt][3])
                        : "r"(a[mt][0]), "r"(a[mt][1]), "r"(a[mt][2]), "r"(a[mt][3]),
                          "r"(b0), "r"(bq));
                }
            }
        }
        __syncthreads();
    }

    #pragma unroll
    for (int mt = 0; mt < 2; mt++) {
        int row0 = blockM * 128 + warpM * 32 + mt * 16 + g;
        #pragma unroll
        for (int nt = 0; nt < 8; nt++) {
            int col = blockN * 128 + warpN * 64 + nt * 8 + 2 * tg;
            float bA = b1[col], bBv = b1[col + 1];
            size_t base0 = (size_t)row0 * HH + col;
            size_t base1 = (size_t)(row0 + 8) * HH + col;
            g_Z[base0]     = c[mt][nt][0] + bA;
            g_Z[base0 + 1] = c[mt][nt][1] + bBv;
            g_Z[base1]     = c[mt][nt][2] + bA;
            g_Z[base1 + 1] = c[mt][nt][3] + bBv;
        }
    }
}

// ---------------------------------------------------------------------------
// Kernel 2a (per iter): partial pooling.
// grid (NSPLIT, BB); CTA (s, b) handles n in [s*64, s*64+64).
// part[b*8+s][d] = sum over those 64 rows of q[b,n]*V[b,n,d]
// ---------------------------------------------------------------------------
__global__ __launch_bounds__(256) void pool_partial_kernel(
    const float* __restrict__ q,    // [B, N]
    const float* __restrict__ V)    // [B, N, D]
{
    const int s   = blockIdx.x;     // 0..7
    const int b   = blockIdx.y;     // 0..63
    const int tid = threadIdx.x;
    const int d4  = tid & 63;       // float4 index into D
    const int ns  = tid >> 6;       // 0..3

    __shared__ float qs[64];
    __shared__ float4 part[4][64];

    if (tid < 64) qs[tid] = q[b * NN + s * 64 + tid];
    __syncthreads();

    const float4* __restrict__ V4 = (const float4*)V;
    const int n0 = s * 64;
    float4 acc = make_float4(0.f, 0.f, 0.f, 0.f);
    #pragma unroll
    for (int i = 0; i < 16; i++) {
        int n = n0 + ns + i * 4;
        float qv = qs[n - n0];
        float4 v = V4[(size_t)(b * NN + n) * (DD / 4) + d4];
        acc.x += qv * v.x; acc.y += qv * v.y;
        acc.z += qv * v.z; acc.w += qv * v.w;
    }
    part[ns][d4] = acc;
    __syncthreads();
    if (tid < 64) {
        float4 s0 = part[0][tid], s1 = part[1][tid],
               s2 = part[2][tid], s3 = part[3][tid];
        float4 r = make_float4(s0.x + s1.x + s2.x + s3.x,
                               s0.y + s1.y + s2.y + s3.y,
                               s0.z + s1.z + s2.z + s3.z,
                               s0.w + s1.w + s2.w + s3.w);
        ((float4*)g_part)[(b * NSPLIT + s) * (DD / 4) + tid] = r;
    }
}

// ---------------------------------------------------------------------------
// Kernel 2b (per iter): reduce partials -> pooled, then u = pooled @ W1p.
// grid (BB, 2); blockIdx.y selects h-half. 256 threads, one h each.
// ---------------------------------------------------------------------------
__global__ __launch_bounds__(256) void u_kernel(
    const float* __restrict__ W1,   // [512, 512]; rows 256..511 = W1p
    float* __restrict__ u)          // [B, H]
{
    const int b    = blockIdx.x;
    const int half = blockIdx.y;
    const int tid  = threadIdx.x;

    __shared__ float pooled_s[DD];

    // reduce 8 partials; thread tid handles d = tid (DD == 256 == blockDim)
    float p = 0.f;
    #pragma unroll
    for (int s = 0; s < NSPLIT; s++)
        p += g_part[(b * NSPLIT + s) * DD + tid];
    pooled_s[tid] = p;
    __syncthreads();

    const float* __restrict__ W1p = W1 + (size_t)DD * HH;
    const int h = half * 256 + tid;
    float a = 0.f;
    #pragma unroll 8
    for (int d = 0; d < DD; d++)
        a += pooled_s[d] * W1p[(size_t)d * HH + h];
    u[b * HH + h] = a;
}

// ---------------------------------------------------------------------------
// Kernel 3 (per iter): q'[b,n] = sigmoid( sum_h relu(Z[b,n,h]+u[b,h])*w2[h] + b2 )
// ---------------------------------------------------------------------------
__global__ __launch_bounds__(256) void score_kernel(
    const float* __restrict__ u,    // [B, H]
    const float* __restrict__ W2,   // [H]
    const float* __restrict__ b2,   // [1]
    float* __restrict__ qout)       // [B, N]
{
    const int blk = blockIdx.x;            // 0..1023
    const int b   = blk >> 4;
    const int nb  = (blk & 15) * 32;
    const int tid = threadIdx.x;
    const int w   = tid >> 5;
    const int l   = tid & 31;

    __shared__ float4 us4[HH / 4];
    __shared__ float4 w24[HH / 4];
    if (tid < HH / 4) {
        us4[tid] = ((const float4*)(u + b * HH))[tid];
        w24[tid] = ((const float4*)W2)[tid];
    }
    __syncthreads();

    const float b2v = b2[0];

    #pragma unroll
    for (int r = 0; r < 4; r++) {
        const int n = nb + w * 4 + r;
        const float4* __restrict__ z4 =
            (const float4*)(g_Z + (size_t)(b * NN + n) * HH);
        float acc = 0.f;
        #pragma unroll
        for (int k = 0; k < 4; k++) {
            int idx = l + 32 * k;
            float4 z  = z4[idx];
            float4 uu = us4[idx];
            float4 ww = w24[idx];
            acc += fmaxf(z.x + uu.x, 0.f) * ww.x;
            acc += fmaxf(z.y + uu.y, 0.f) * ww.y;
            acc += fmaxf(z.z + uu.z, 0.f) * ww.z;
            acc += fmaxf(z.w + uu.w, 0.f) * ww.w;
        }
        #pragma unroll
        for (int off = 16; off; off >>= 1)
            acc += __shfl_xor_sync(0xffffffffu, acc, off);
        if (l == 0) {
            float s = acc + b2v;
            qout[b * NN + n] = 1.f / (1.f + expf(-s));
        }
    }
}

// ---------------------------------------------------------------------------
extern "C" void kernel_launch(void* const* d_in, const int* in_sizes, int n_in,
                              void* d_out, int out_size) {
    const float* q_init = (const float*)d_in[0];  // [B,N]
    const float* V      = (const float*)d_in[1];  // [B,N,D]
    const float* W1     = (const float*)d_in[2];  // [2D,H]
    const float* b1     = (const float*)d_in[3];  // [H]
    const float* W2     = (const float*)d_in[4];  // [H]
    const float* b2     = (const float*)d_in[5];  // [1]
    float* out = (float*)d_out;

    float* g_q_p;
    float* g_u_p;
    cudaGetSymbolAddress((void**)&g_q_p, g_q);
    cudaGetSymbolAddress((void**)&g_u_p, g_u);

    zgemm_kernel<<<dim3(4, 256), 256>>>(V, W1, b1);

    for (int it = 0; it < MAX_ITER; it++) {
        const float* qin = (it == 0) ? q_init : g_q_p;
        pool_partial_kernel<<<dim3(NSPLIT, BB), 256>>>(qin, V);
        u_kernel<<<dim3(BB, 2), 256>>>(W1, g_u_p);
        float* qdst = (it == MAX_ITER - 1) ? out : g_q_p;
        score_kernel<<<BB * 16, 256>>>(g_u_p, W2, b2, qdst);
    }
}

// round 4
// speedup vs baseline: 2.8678x; 1.8089x over previous
#include <cuda_runtime.h>
#include <cuda_fp16.h>
#include <cuda_bf16.h>
#include <math.h>

// Problem dims
#define BB 64
#define NN 512
#define DD 256
#define HH 512
#define MAX_ITER 20
#define NSPLIT 8               // pooling splits over N

#define ZM (BB * NN)           // 32768

// Scratch (allocation-free: __device__ globals)
__device__ __half g_Z[(size_t)ZM * HH];       // 32 MiB: Z[b,n,h] = V@W1v + b1 (fp16)
__device__ float  g_q[BB * NN];
__device__ float  g_u[BB * HH];
__device__ float  g_part[BB * NSPLIT * DD];   // pooling partials

__device__ __forceinline__ unsigned f2tf32(float x) {
    unsigned r;
    asm("cvt.rna.tf32.f32 %0, %1;" : "=r"(r) : "f"(x));
    return r;
}

#define CP_ASYNC16(dst, src) \
    asm volatile("cp.async.cg.shared.global [%0], [%1], 16;\n" :: "r"(dst), "l"(src))
#define CP_COMMIT() asm volatile("cp.async.commit_group;\n" ::)
#define CP_WAIT(n)  asm volatile("cp.async.wait_group %0;\n" :: "n"(n))

// ---------------------------------------------------------------------------
// Kernel 1 (once): Z = V @ W1v + b1  (M=32768, K=256, N=512), TF32 mma.sync
// CTA tile 128x128, BK=16, cp.async double-buffered. 8 warps, warp tile 32x64.
// ---------------------------------------------------------------------------
#define BK 16
#define APAD 20   // row stride (floats) for As, 16B-aligned
#define BPAD 136  // row stride (floats) for Bs

__global__ __launch_bounds__(256) void zgemm_kernel(
    const float* __restrict__ V,    // [ZM, 256]
    const float* __restrict__ W1,   // [512, 512]; top 256 rows = W1v
    const float* __restrict__ b1)   // [512]
{
    __shared__ float As[2][128][APAD];
    __shared__ float Bs[2][BK][BPAD];

    const int tid   = threadIdx.x;
    const int warp  = tid >> 5;
    const int lane  = tid & 31;
    const int g     = lane >> 2;
    const int tg    = lane & 3;
    const int warpM = warp >> 1;
    const int warpN = warp & 1;

    const int blockN = blockIdx.x;   // 0..3
    const int blockM = blockIdx.y;   // 0..255

    // cp.async source/dest coords (per thread: 2 chunks of A, 2 of B)
    const int aRow0 = (tid * 1) >> 2;          // chunks: idx = tid + t*256
    // A: 512 chunks (128 rows x 4). B: 512 chunks (16 rows x 32).
    const float* Abase = V + (size_t)blockM * 128 * DD;
    const float* Bbase = W1 + blockN * 128;

    float c[2][8][4];
    #pragma unroll
    for (int mt = 0; mt < 2; mt++)
        #pragma unroll
        for (int nt = 0; nt < 8; nt++)
            #pragma unroll
            for (int i = 0; i < 4; i++) c[mt][nt][i] = 0.f;

    unsigned sA = (unsigned)__cvta_generic_to_shared(&As[0][0][0]);
    unsigned sB = (unsigned)__cvta_generic_to_shared(&Bs[0][0][0]);
    const unsigned stageA = 128 * APAD * 4;
    const unsigned stageB = BK * BPAD * 4;

    auto issue_loads = [&](int k0, int st) {
        #pragma unroll
        for (int t = 0; t < 2; t++) {
            int idx = tid + t * 256;
            int r = idx >> 2, kc = idx & 3;             // A: row, 16B chunk
            CP_ASYNC16(sA + st * stageA + (r * APAD + kc * 4) * 4,
                       Abase + (size_t)r * DD + k0 + kc * 4);
        }
        #pragma unroll
        for (int t = 0; t < 2; t++) {
            int idx = tid + t * 256;
            int r = idx >> 5, cc = idx & 31;            // B: row, 16B chunk
            CP_ASYNC16(sB + st * stageB + (r * BPAD + cc * 4) * 4,
                       Bbase + (size_t)(k0 + r) * HH + cc * 4);
        }
        CP_COMMIT();
    };

    issue_loads(0, 0);

    const int NCHUNK = DD / BK;   // 16
    for (int ch = 0; ch < NCHUNK; ch++) {
        int st = ch & 1;
        if (ch + 1 < NCHUNK) {
            issue_loads((ch + 1) * BK, st ^ 1);
            CP_WAIT(1);
        } else {
            CP_WAIT(0);
        }
        __syncthreads();

        #pragma unroll
        for (int kk = 0; kk < BK; kk += 8) {
            unsigned a[2][4];
            #pragma unroll
            for (int mt = 0; mt < 2; mt++) {
                int ar = warpM * 32 + mt * 16 + g;
                a[mt][0] = f2tf32(As[st][ar][kk + tg]);
                a[mt][1] = f2tf32(As[st][ar + 8][kk + tg]);
                a[mt][2] = f2tf32(As[st][ar][kk + tg + 4]);
                a[mt][3] = f2tf32(As[st][ar + 8][kk + tg + 4]);
            }
            #pragma unroll
            for (int nt = 0; nt < 8; nt++) {
                int bc = warpN * 64 + nt * 8 + g;
                unsigned b0 = f2tf32(Bs[st][kk + tg][bc]);
                unsigned bq = f2tf32(Bs[st][kk + tg + 4][bc]);
                #pragma unroll
                for (int mt = 0; mt < 2; mt++) {
                    asm volatile(
                        "mma.sync.aligned.m16n8k8.row.col.f32.tf32.tf32.f32 "
                        "{%0,%1,%2,%3}, {%4,%5,%6,%7}, {%8,%9}, {%0,%1,%2,%3};"
                        : "+f"(c[mt][nt][0]), "+f"(c[mt][nt][1]),
                          "+f"(c[mt][nt][2]), "+f"(c[mt][nt][3])
                        : "r"(a[mt][0]), "r"(a[mt][1]), "r"(a[mt][2]), "r"(a[mt][3]),
                          "r"(b0), "r"(bq));
                }
            }
        }
        __syncthreads();
    }

    // epilogue: Z = half(c + b1[col]) — adjacent col pairs -> half2 stores
    __half2* Z2 = (__half2*)g_Z;
    #pragma unroll
    for (int mt = 0; mt < 2; mt++) {
        int row0 = blockM * 128 + warpM * 32 + mt * 16 + g;
        #pragma unroll
        for (int nt = 0; nt < 8; nt++) {
            int col = blockN * 128 + warpN * 64 + nt * 8 + 2 * tg;
            float bA = b1[col], bBv = b1[col + 1];
            Z2[((size_t)row0 * HH + col) >> 1] =
                __floats2half2_rn(c[mt][nt][0] + bA, c[mt][nt][1] + bBv);
            Z2[((size_t)(row0 + 8) * HH + col) >> 1] =
                __floats2half2_rn(c[mt][nt][2] + bA, c[mt][nt][3] + bBv);
        }
    }
}

// ---------------------------------------------------------------------------
// Kernel 2a (per iter): partial pooling. grid (NSPLIT, BB).
// ---------------------------------------------------------------------------
__global__ __launch_bounds__(256) void pool_partial_kernel(
    const float* __restrict__ q,    // [B, N]
    const float* __restrict__ V)    // [B, N, D]
{
    const int s   = blockIdx.x;     // 0..7
    const int b   = blockIdx.y;     // 0..63
    const int tid = threadIdx.x;
    const int d4  = tid & 63;
    const int ns  = tid >> 6;

    __shared__ float qs[64];
    __shared__ float4 part[4][64];

    if (tid < 64) qs[tid] = q[b * NN + s * 64 + tid];
    __syncthreads();

    const float4* __restrict__ V4 = (const float4*)V;
    const int n0 = s * 64;
    float4 acc = make_float4(0.f, 0.f, 0.f, 0.f);
    #pragma unroll
    for (int i = 0; i < 16; i++) {
        int n = n0 + ns + i * 4;
        float qv = qs[n - n0];
        float4 v = V4[(size_t)(b * NN + n) * (DD / 4) + d4];
        acc.x += qv * v.x; acc.y += qv * v.y;
        acc.z += qv * v.z; acc.w += qv * v.w;
    }
    part[ns][d4] = acc;
    __syncthreads();
    if (tid < 64) {
        float4 s0 = part[0][tid], s1 = part[1][tid],
               s2 = part[2][tid], s3 = part[3][tid];
        float4 r = make_float4(s0.x + s1.x + s2.x + s3.x,
                               s0.y + s1.y + s2.y + s3.y,
                               s0.z + s1.z + s2.z + s3.z,
                               s0.w + s1.w + s2.w + s3.w);
        ((float4*)g_part)[(b * NSPLIT + s) * (DD / 4) + tid] = r;
    }
}

// ---------------------------------------------------------------------------
// Kernel 2b (per iter): reduce partials -> pooled, u = pooled @ W1p.
// ---------------------------------------------------------------------------
__global__ __launch_bounds__(256) void u_kernel(
    const float* __restrict__ W1,   // rows 256..511 = W1p
    float* __restrict__ u)          // [B, H]
{
    const int b    = blockIdx.x;
    const int half = blockIdx.y;
    const int tid  = threadIdx.x;

    __shared__ float pooled_s[DD];

    float p = 0.f;
    #pragma unroll
    for (int s = 0; s < NSPLIT; s++)
        p += g_part[(b * NSPLIT + s) * DD + tid];
    pooled_s[tid] = p;
    __syncthreads();

    const float* __restrict__ W1p = W1 + (size_t)DD * HH;
    const int h = half * 256 + tid;
    float a = 0.f;
    #pragma unroll 8
    for (int d = 0; d < DD; d++)
        a += pooled_s[d] * W1p[(size_t)d * HH + h];
    u[b * HH + h] = a;
}

// ---------------------------------------------------------------------------
// Kernel 3 (per iter): q'[b,n] = sigmoid( sum_h relu(Z+u)*w2 + b2 ), Z fp16
// ---------------------------------------------------------------------------
__global__ __launch_bounds__(256) void score_kernel(
    const float* __restrict__ u,    // [B, H]
    const float* __restrict__ W2,   // [H]
    const float* __restrict__ b2,   // [1]
    float* __restrict__ qout)       // [B, N]
{
    const int blk = blockIdx.x;            // 0..1023
    const int b   = blk >> 4;
    const int nb  = (blk & 15) * 32;
    const int tid = threadIdx.x;
    const int w   = tid >> 5;
    const int l   = tid & 31;

    __shared__ float4 us4[HH / 4];
    __shared__ float4 w24[HH / 4];
    if (tid < HH / 4) {
        us4[tid] = ((const float4*)(u + b * HH))[tid];
        w24[tid] = ((const float4*)W2)[tid];
    }
    __syncthreads();

    const float b2v = b2[0];

    #pragma unroll
    for (int r = 0; r < 4; r++) {
        const int n = nb + w * 4 + r;
        const uint4* __restrict__ z8 =
            (const uint4*)(g_Z + (size_t)(b * NN + n) * HH);  // 8 halves per uint4
        float acc = 0.f;
        #pragma unroll
        for (int k = 0; k < 2; k++) {
            int idx = l + 32 * k;          // uint4 index, h = idx*8
            uint4 zr = z8[idx];
            float4 u0 = us4[idx * 2], u1 = us4[idx * 2 + 1];
            float4 w0 = w24[idx * 2], w1 = w24[idx * 2 + 1];
            float2 za = __half22float2(*(__half2*)&zr.x);
            float2 zb = __half22float2(*(__half2*)&zr.y);
            float2 zc = __half22float2(*(__half2*)&zr.z);
            float2 zd = __half22float2(*(__half2*)&zr.w);
            acc += fmaxf(za.x + u0.x, 0.f) * w0.x;
            acc += fmaxf(za.y + u0.y, 0.f) * w0.y;
            acc += fmaxf(zb.x + u0.z, 0.f) * w0.z;
            acc += fmaxf(zb.y + u0.w, 0.f) * w0.w;
            acc += fmaxf(zc.x + u1.x, 0.f) * w1.x;
            acc += fmaxf(zc.y + u1.y, 0.f) * w1.y;
            acc += fmaxf(zd.x + u1.z, 0.f) * w1.z;
            acc += fmaxf(zd.y + u1.w, 0.f) * w1.w;
        }
        #pragma unroll
        for (int off = 16; off; off >>= 1)
            acc += __shfl_xor_sync(0xffffffffu, acc, off);
        if (l == 0) {
            float s = acc + b2v;
            qout[b * NN + n] = 1.f / (1.f + expf(-s));
        }
    }
}

// ---------------------------------------------------------------------------
extern "C" void kernel_launch(void* const* d_in, const int* in_sizes, int n_in,
                              void* d_out, int out_size) {
    const float* q_init = (const float*)d_in[0];  // [B,N]
    const float* V      = (const float*)d_in[1];  // [B,N,D]
    const float* W1     = (const float*)d_in[2];  // [2D,H]
    const float* b1     = (const float*)d_in[3];  // [H]
    const float* W2     = (const float*)d_in[4];  // [H]
    const float* b2     = (const float*)d_in[5];  // [1]
    float* out = (float*)d_out;

    float* g_q_p;
    float* g_u_p;
    cudaGetSymbolAddress((void**)&g_q_p, g_q);
    cudaGetSymbolAddress((void**)&g_u_p, g_u);

    zgemm_kernel<<<dim3(4, 256), 256>>>(V, W1, b1);

    for (int it = 0; it < MAX_ITER; it++) {
        const float* qin = (it == 0) ? q_init : g_q_p;
        pool_partial_kernel<<<dim3(NSPLIT, BB), 256>>>(qin, V);
        u_kernel<<<dim3(BB, 2), 256>>>(W1, g_u_p);
        float* qdst = (it == MAX_ITER - 1) ? out : g_q_p;
        score_kernel<<<BB * 16, 256>>>(g_u_p, W2, b2, qdst);
    }
}